// round 4
// baseline (speedup 1.0000x reference)
#include <cuda_runtime.h>
#include <math.h>
#include <stdint.h>

// Problem constants
#define BB 2
#define TT 2048
#define EE 1024
#define HH 16
#define HD 64
#define DFF 4096
#define NTOK (BB*TT)          // 4096
#define BHN (BB*HH)           // 32

// ---------------- scratch (device globals; no allocation allowed) ----------------
__device__ float g_h   [NTOK*EE];
__device__ float g_wqkv[EE*3*EE];
__device__ float g_qkv [NTOK*3*EE];
__device__ float g_o   [NTOK*EE];
__device__ float g_x2  [NTOK*EE];
__device__ float g_h2  [NTOK*EE];
__device__ float g_ffn [NTOK*DFF];

// ---------------- helpers ----------------
__device__ __forceinline__ uint32_t cvt_tf32(float x) {
    uint32_t r;
    asm("cvt.rna.tf32.f32 %0, %1;" : "=r"(r) : "f"(x));
    return r;
}
__device__ __forceinline__ float cvt_tf32f(float x) {
    return __uint_as_float(cvt_tf32(x));
}
__device__ __forceinline__ void cp16(void* s, const void* g) {
    uint32_t sa = (uint32_t)__cvta_generic_to_shared(s);
    asm volatile("cp.async.cg.shared.global [%0], [%1], 16;" :: "r"(sa), "l"(g));
}
__device__ __forceinline__ void cp_commit() { asm volatile("cp.async.commit_group;"); }
template<int N> __device__ __forceinline__ void cp_wait() {
    asm volatile("cp.async.wait_group %0;" :: "n"(N));
}
__device__ __forceinline__ void mma_tf32(float acc[4], const uint32_t a[4],
                                         uint32_t b0, uint32_t b1) {
    asm volatile(
        "mma.sync.aligned.m16n8k8.row.col.f32.tf32.tf32.f32 "
        "{%0,%1,%2,%3},{%4,%5,%6,%7},{%8,%9},{%0,%1,%2,%3};"
        : "+f"(acc[0]), "+f"(acc[1]), "+f"(acc[2]), "+f"(acc[3])
        : "r"(a[0]), "r"(a[1]), "r"(a[2]), "r"(a[3]), "r"(b0), "r"(b1));
}

// ---------------- LayerNorm ----------------
__global__ void ln_kernel(const float* __restrict__ x,
                          const float* __restrict__ gamma,
                          const float* __restrict__ beta,
                          float* __restrict__ y)
{
    int row = blockIdx.x;
    const float* xr = x + (size_t)row * EE;
    float* yr = y + (size_t)row * EE;
    int tid = threadIdx.x;
    __shared__ float red[256];

    float s = 0.f;
    for (int i = tid; i < EE; i += 256) s += xr[i];
    red[tid] = s; __syncthreads();
    for (int o = 128; o > 0; o >>= 1) { if (tid < o) red[tid] += red[tid + o]; __syncthreads(); }
    float mean = red[0] * (1.0f / EE);
    __syncthreads();

    float v = 0.f;
    for (int i = tid; i < EE; i += 256) { float d = xr[i] - mean; v += d * d; }
    red[tid] = v; __syncthreads();
    for (int o = 128; o > 0; o >>= 1) { if (tid < o) red[tid] += red[tid + o]; __syncthreads(); }
    float inv = rsqrtf(red[0] * (1.0f / EE) + 1e-5f);

    for (int i = tid; i < EE; i += 256)
        yr[i] = (xr[i] - mean) * inv * gamma[i] + beta[i];
}

// ---------------- pack wq/wk/wv [H,E,hd] -> [E, 3E] ----------------
__global__ void pack_w_kernel(const float* __restrict__ wq,
                              const float* __restrict__ wk,
                              const float* __restrict__ wv,
                              float* __restrict__ out)
{
    int idx = blockIdx.x * blockDim.x + threadIdx.x;
    const int total = 3 * EE * EE;
    if (idx >= total) return;
    int part = idx / (EE * EE);
    int rem  = idx % (EE * EE);
    int e = rem / EE;
    int c = rem % EE;
    const float* w = (part == 0) ? wq : (part == 1) ? wk : wv;
    out[(size_t)e * (3 * EE) + part * EE + c] =
        w[(size_t)(c >> 6) * (EE * HD) + (size_t)e * HD + (c & 63)];
}

// ---------------- tf32 GEMM, 4-stage cp.async pipeline -----------
// Block 128x128x16, 8 warps (4x2), warp tile 32x64 via m16n8k8.
// EPI: 0 = none; 2 = relu(+bias); 3 = +bias +res
#define MM_STAGES 4
#define MM_SMEM ((MM_STAGES*128*20 + MM_STAGES*16*136) * 4)

template <int EPI>
__global__ void __launch_bounds__(256, 2)
mm_tf32(const float* __restrict__ A,
        const float* __restrict__ B,
        const float* __restrict__ bias,
        const float* __restrict__ res,
        float* __restrict__ C,
        int M, int N, int K)
{
    const int BM = 128, BN = 128, BK = 16;
    extern __shared__ float smemf[];
    float (*As)[BM][BK + 4]  = (float(*)[BM][BK + 4])smemf;
    float (*Bs)[BK][BN + 8]  = (float(*)[BK][BN + 8])(smemf + MM_STAGES * BM * (BK + 4));

    int tid = threadIdx.x;
    int lane = tid & 31, wid = tid >> 5;
    int wm = wid >> 1, wn = wid & 1;
    int g = lane >> 2, c = lane & 3;
    int rowBase = blockIdx.y * BM;
    int colBase = blockIdx.x * BN;

    float acc[2][8][4];
    #pragma unroll
    for (int i = 0; i < 2; i++)
        #pragma unroll
        for (int j = 0; j < 8; j++)
            #pragma unroll
            for (int k = 0; k < 4; k++) acc[i][j][k] = 0.f;

    auto load_stage = [&](int buf, int kk) {
        #pragma unroll
        for (int i = 0; i < 2; i++) {
            int idx = i * 256 + tid;
            int m = idx >> 2, ch = idx & 3;
            cp16(&As[buf][m][ch * 4], A + (size_t)(rowBase + m) * K + kk + ch * 4);
        }
        #pragma unroll
        for (int i = 0; i < 2; i++) {
            int idx = i * 256 + tid;
            int r = idx >> 5, ch = idx & 31;
            cp16(&Bs[buf][r][ch * 4], B + (size_t)(kk + r) * N + colBase + ch * 4);
        }
        cp_commit();
    };

    // prologue: stages 0..2 in flight
    #pragma unroll
    for (int s = 0; s < MM_STAGES - 1; s++) load_stage(s, s * BK);

    int nk = K / BK;
    for (int k0 = 0; k0 < nk; k0++) {
        cp_wait<MM_STAGES - 2>();      // stage k0 complete
        __syncthreads();               // all warps done with stage (k0-1) compute

        int nxt = k0 + MM_STAGES - 1;
        if (nxt < nk) load_stage(nxt % MM_STAGES, nxt * BK);
        else          cp_commit();     // keep group count aligned

        int cur = k0 % MM_STAGES;
        #pragma unroll
        for (int ks = 0; ks < 2; ks++) {
            int kb = ks * 8;
            uint32_t af[2][4];
            #pragma unroll
            for (int mt = 0; mt < 2; mt++) {
                int m0 = wm * 32 + mt * 16;
                af[mt][0] = cvt_tf32(As[cur][m0 + g    ][kb + c    ]);
                af[mt][1] = cvt_tf32(As[cur][m0 + g + 8][kb + c    ]);
                af[mt][2] = cvt_tf32(As[cur][m0 + g    ][kb + c + 4]);
                af[mt][3] = cvt_tf32(As[cur][m0 + g + 8][kb + c + 4]);
            }
            uint32_t bf[8][2];
            #pragma unroll
            for (int nt = 0; nt < 8; nt++) {
                int n0 = wn * 64 + nt * 8;
                bf[nt][0] = cvt_tf32(Bs[cur][kb + c    ][n0 + g]);
                bf[nt][1] = cvt_tf32(Bs[cur][kb + c + 4][n0 + g]);
            }
            #pragma unroll
            for (int mt = 0; mt < 2; mt++)
                #pragma unroll
                for (int nt = 0; nt < 8; nt++)
                    mma_tf32(acc[mt][nt], af[mt], bf[nt][0], bf[nt][1]);
        }
    }

    #pragma unroll
    for (int mt = 0; mt < 2; mt++) {
        int row0 = rowBase + wm * 32 + mt * 16 + g;
        #pragma unroll
        for (int nt = 0; nt < 8; nt++) {
            int col = colBase + wn * 64 + nt * 8 + c * 2;
            float v0 = acc[mt][nt][0], v1 = acc[mt][nt][1];
            float v2 = acc[mt][nt][2], v3 = acc[mt][nt][3];
            if (EPI >= 1) {
                float b0 = bias[col], b1 = bias[col + 1];
                v0 += b0; v1 += b1; v2 += b0; v3 += b1;
            }
            if (EPI == 2) {
                v0 = fmaxf(v0, 0.f); v1 = fmaxf(v1, 0.f);
                v2 = fmaxf(v2, 0.f); v3 = fmaxf(v3, 0.f);
            }
            if (EPI == 3) {
                v0 += res[(size_t)row0 * N + col];
                v1 += res[(size_t)row0 * N + col + 1];
                v2 += res[(size_t)(row0 + 8) * N + col];
                v3 += res[(size_t)(row0 + 8) * N + col + 1];
            }
            *reinterpret_cast<float2*>(&C[(size_t)row0 * N + col])       = make_float2(v0, v1);
            *reinterpret_cast<float2*>(&C[(size_t)(row0 + 8) * N + col]) = make_float2(v2, v3);
        }
    }
}

// ---------------- fused flash attention ----------------
// grid: (T/128, BHN); block: 256 (8 warps, 16 query rows each => Br=128)
// Bc = 64. S-accum permuted into PV A-fragments via warp shuffles (no P smem).
__global__ void __launch_bounds__(256, 2)
flash_kernel(const float* __restrict__ qkv, float* __restrict__ o)
{
    __shared__ float Ks[64][68];
    __shared__ float Vs[64][72];

    int bh = blockIdx.y;
    int b = bh >> 4, h = bh & 15;
    int rt = gridDim.x - 1 - blockIdx.x;   // heavy CTAs first
    int q0 = rt * 128;

    int tid = threadIdx.x;
    int lane = tid & 31, wid = tid >> 5;
    int g = lane >> 2, c = lane & 3;
    int wbase = wid * 16;
    int qlo = q0 + wbase;                  // first query row of this warp
    int qhi = qlo + 15;                    // last query row of this warp
    int qg0 = qlo + g;                     // this thread's row (and qg0+8)

    // Q fragments, pre-scaled by 1/sqrt(hd), tf32
    uint32_t qf[8][4];
    const float* Qb = qkv + ((size_t)(b * TT + qlo)) * (3 * EE) + (size_t)h * HD;
    #pragma unroll
    for (int k8 = 0; k8 < 8; k8++) {
        int kb = k8 * 8;
        qf[k8][0] = cvt_tf32(0.125f * Qb[(size_t)g       * (3 * EE) + kb + c]);
        qf[k8][1] = cvt_tf32(0.125f * Qb[(size_t)(g + 8) * (3 * EE) + kb + c]);
        qf[k8][2] = cvt_tf32(0.125f * Qb[(size_t)g       * (3 * EE) + kb + c + 4]);
        qf[k8][3] = cvt_tf32(0.125f * Qb[(size_t)(g + 8) * (3 * EE) + kb + c + 4]);
    }

    float m0 = -INFINITY, m1 = -INFINITY, l0 = 0.f, l1 = 0.f;
    float oacc[8][4];
    #pragma unroll
    for (int nt = 0; nt < 8; nt++)
        #pragma unroll
        for (int k = 0; k < 4; k++) oacc[nt][k] = 0.f;

    int ntiles = 2 * rt + 2;
    for (int st = 0; st < ntiles; st++) {
        __syncthreads();

        // cooperative K,V tile load [64 x 64], tf32 at store
        const float* Kg = qkv + ((size_t)(b * TT + st * 64)) * (3 * EE) + EE + (size_t)h * HD;
        const float* Vg = Kg + EE;
        #pragma unroll
        for (int i = 0; i < 4; i++) {
            int idx = i * 256 + tid;
            int r = idx >> 4, ch = (idx & 15) * 4;
            float4 kv = *(const float4*)(Kg + (size_t)r * (3 * EE) + ch);
            Ks[r][ch]     = cvt_tf32f(kv.x);
            Ks[r][ch + 1] = cvt_tf32f(kv.y);
            Ks[r][ch + 2] = cvt_tf32f(kv.z);
            Ks[r][ch + 3] = cvt_tf32f(kv.w);
            float4 vv = *(const float4*)(Vg + (size_t)r * (3 * EE) + ch);
            Vs[r][ch]     = cvt_tf32f(vv.x);
            Vs[r][ch + 1] = cvt_tf32f(vv.y);
            Vs[r][ch + 2] = cvt_tf32f(vv.z);
            Vs[r][ch + 3] = cvt_tf32f(vv.w);
        }
        __syncthreads();

        if (st * 64 > qhi) continue;   // tile fully in the future for this warp

        // S = Q @ K^T : 16 x 64 per warp
        float sacc[8][4];
        #pragma unroll
        for (int nt = 0; nt < 8; nt++)
            #pragma unroll
            for (int k = 0; k < 4; k++) sacc[nt][k] = 0.f;

        #pragma unroll
        for (int k8 = 0; k8 < 8; k8++) {
            int kb = k8 * 8;
            #pragma unroll
            for (int nt = 0; nt < 8; nt++) {
                uint32_t b0 = __float_as_uint(Ks[nt * 8 + g][kb + c]);
                uint32_t b1 = __float_as_uint(Ks[nt * 8 + g][kb + c + 4]);
                mma_tf32(sacc[nt], qf[k8], b0, b1);
            }
        }

        // causal mask (only on warp's boundary tiles)
        if (st * 64 + 63 > qlo) {
            #pragma unroll
            for (int nt = 0; nt < 8; nt++) {
                int kl = st * 64 + nt * 8 + 2 * c;
                if (kl     > qg0)     sacc[nt][0] = -1e30f;
                if (kl + 1 > qg0)     sacc[nt][1] = -1e30f;
                if (kl     > qg0 + 8) sacc[nt][2] = -1e30f;
                if (kl + 1 > qg0 + 8) sacc[nt][3] = -1e30f;
            }
        }

        // online softmax
        float mx0 = -1e30f, mx1 = -1e30f;
        #pragma unroll
        for (int nt = 0; nt < 8; nt++) {
            mx0 = fmaxf(mx0, fmaxf(sacc[nt][0], sacc[nt][1]));
            mx1 = fmaxf(mx1, fmaxf(sacc[nt][2], sacc[nt][3]));
        }
        mx0 = fmaxf(mx0, __shfl_xor_sync(0xffffffffu, mx0, 1));
        mx0 = fmaxf(mx0, __shfl_xor_sync(0xffffffffu, mx0, 2));
        mx1 = fmaxf(mx1, __shfl_xor_sync(0xffffffffu, mx1, 1));
        mx1 = fmaxf(mx1, __shfl_xor_sync(0xffffffffu, mx1, 2));

        float mn0 = fmaxf(m0, mx0), mn1 = fmaxf(m1, mx1);
        float al0 = __expf(m0 - mn0), al1 = __expf(m1 - mn1);
        m0 = mn0; m1 = mn1;

        float rs0 = 0.f, rs1 = 0.f;
        #pragma unroll
        for (int nt = 0; nt < 8; nt++) {
            float p0 = __expf(sacc[nt][0] - m0);
            float p1 = __expf(sacc[nt][1] - m0);
            float p2 = __expf(sacc[nt][2] - m1);
            float p3 = __expf(sacc[nt][3] - m1);
            rs0 += p0 + p1; rs1 += p2 + p3;
            sacc[nt][0] = cvt_tf32f(p0); sacc[nt][1] = cvt_tf32f(p1);
            sacc[nt][2] = cvt_tf32f(p2); sacc[nt][3] = cvt_tf32f(p3);
        }
        rs0 += __shfl_xor_sync(0xffffffffu, rs0, 1);
        rs0 += __shfl_xor_sync(0xffffffffu, rs0, 2);
        rs1 += __shfl_xor_sync(0xffffffffu, rs1, 1);
        rs1 += __shfl_xor_sync(0xffffffffu, rs1, 2);
        l0 = l0 * al0 + rs0;
        l1 = l1 * al1 + rs1;

        #pragma unroll
        for (int nt = 0; nt < 8; nt++) {
            oacc[nt][0] *= al0; oacc[nt][1] *= al0;
            oacc[nt][2] *= al1; oacc[nt][3] *= al1;
        }

        // O += P @ V : permute S-accum into A fragments via shuffles
        bool odd = (c & 1);
        int src0 = 4 * g + (c >> 1);
        int src2 = src0 + 2;
        #pragma unroll
        for (int kb8 = 0; kb8 < 8; kb8++) {
            float x0 = __shfl_sync(0xffffffffu, sacc[kb8][0], src0);
            float x1 = __shfl_sync(0xffffffffu, sacc[kb8][1], src0);
            float y0 = __shfl_sync(0xffffffffu, sacc[kb8][2], src0);
            float y1 = __shfl_sync(0xffffffffu, sacc[kb8][3], src0);
            float x0b = __shfl_sync(0xffffffffu, sacc[kb8][0], src2);
            float x1b = __shfl_sync(0xffffffffu, sacc[kb8][1], src2);
            float y0b = __shfl_sync(0xffffffffu, sacc[kb8][2], src2);
            float y1b = __shfl_sync(0xffffffffu, sacc[kb8][3], src2);
            uint32_t af[4];
            af[0] = __float_as_uint(odd ? x1  : x0 );
            af[1] = __float_as_uint(odd ? y1  : y0 );
            af[2] = __float_as_uint(odd ? x1b : x0b);
            af[3] = __float_as_uint(odd ? y1b : y0b);
            int kb = kb8 * 8;
            #pragma unroll
            for (int nt = 0; nt < 8; nt++) {
                uint32_t b0 = __float_as_uint(Vs[kb + c    ][nt * 8 + g]);
                uint32_t b1 = __float_as_uint(Vs[kb + c + 4][nt * 8 + g]);
                mma_tf32(oacc[nt], af, b0, b1);
            }
        }
    }

    // epilogue
    float i0 = 1.0f / l0, i1 = 1.0f / l1;
    float* Ob = o + ((size_t)(b * TT + qlo)) * EE + (size_t)h * HD;
    #pragma unroll
    for (int nt = 0; nt < 8; nt++) {
        int col = nt * 8 + 2 * c;
        *(float2*)&Ob[(size_t)g * EE + col] =
            make_float2(oacc[nt][0] * i0, oacc[nt][1] * i0);
        *(float2*)&Ob[(size_t)(g + 8) * EE + col] =
            make_float2(oacc[nt][2] * i1, oacc[nt][3] * i1);
    }
}

// ---------------- launcher ----------------
extern "C" void kernel_launch(void* const* d_in, const int* in_sizes, int n_in,
                              void* d_out, int out_size)
{
    const float* x      = (const float*)d_in[0];
    const float* wq     = (const float*)d_in[1];
    const float* wk     = (const float*)d_in[2];
    const float* wv     = (const float*)d_in[3];
    const float* w_proj = (const float*)d_in[4];
    const float* b_proj = (const float*)d_in[5];
    const float* gamma1 = (const float*)d_in[6];
    const float* beta1  = (const float*)d_in[7];
    const float* gamma2 = (const float*)d_in[8];
    const float* beta2  = (const float*)d_in[9];
    const float* w1     = (const float*)d_in[10];
    const float* b1     = (const float*)d_in[11];
    const float* w2     = (const float*)d_in[12];
    const float* b2     = (const float*)d_in[13];
    float* out = (float*)d_out;

    float *p_h, *p_wqkv, *p_qkv, *p_o, *p_x2, *p_h2, *p_ffn;
    cudaGetSymbolAddress((void**)&p_h,    g_h);
    cudaGetSymbolAddress((void**)&p_wqkv, g_wqkv);
    cudaGetSymbolAddress((void**)&p_qkv,  g_qkv);
    cudaGetSymbolAddress((void**)&p_o,    g_o);
    cudaGetSymbolAddress((void**)&p_x2,   g_x2);
    cudaGetSymbolAddress((void**)&p_h2,   g_h2);
    cudaGetSymbolAddress((void**)&p_ffn,  g_ffn);

    cudaFuncSetAttribute(mm_tf32<0>, cudaFuncAttributeMaxDynamicSharedMemorySize, MM_SMEM);
    cudaFuncSetAttribute(mm_tf32<2>, cudaFuncAttributeMaxDynamicSharedMemorySize, MM_SMEM);
    cudaFuncSetAttribute(mm_tf32<3>, cudaFuncAttributeMaxDynamicSharedMemorySize, MM_SMEM);

    // 1) LN1
    ln_kernel<<<NTOK, 256>>>(x, gamma1, beta1, p_h);
    // 2) pack per-head weights
    pack_w_kernel<<<(3 * EE * EE) / 256, 256>>>(wq, wk, wv, p_wqkv);
    // 3) QKV = h @ Wqkv
    mm_tf32<0><<<dim3(3 * EE / 128, NTOK / 128), 256, MM_SMEM>>>(p_h, p_wqkv, nullptr, nullptr, p_qkv, NTOK, 3 * EE, EE);
    // 4-6) fused flash attention
    flash_kernel<<<dim3(TT / 128, BHN), 256>>>(p_qkv, p_o);
    // 7) x2 = h + O @ w_proj + b_proj
    mm_tf32<3><<<dim3(EE / 128, NTOK / 128), 256, MM_SMEM>>>(p_o, w_proj, b_proj, p_h, p_x2, NTOK, EE, EE);
    // 8) LN2
    ln_kernel<<<NTOK, 256>>>(p_x2, gamma2, beta2, p_h2);
    // 9) ffn = relu(h2 @ w1 + b1)
    mm_tf32<2><<<dim3(DFF / 128, NTOK / 128), 256, MM_SMEM>>>(p_h2, w1, b1, nullptr, p_ffn, NTOK, DFF, EE);
    // 10) out = h2 + ffn @ w2 + b2
    mm_tf32<3><<<dim3(EE / 128, NTOK / 128), 256, MM_SMEM>>>(p_ffn, w2, b2, p_h2, out, NTOK, EE, DFF);
}